// round 10
// baseline (speedup 1.0000x reference)
#include <cuda_runtime.h>
#include <cuda_bf16.h>
#include <cuda_fp8.h>
#include <math.h>
#include <stdint.h>

#define BB 64
#define TT 512
#define DIN 862
#define HH 1024
#define GG 4096

#define NCTA 128

// ---------------- scratch (allocation-free rule: __device__ globals) ----------------
static __device__ float g_xg[(size_t)TT * BB * GG];          // [T*B][G] gate preactivations
static __device__ unsigned g_gen;
static __device__ unsigned g_cnt;
static __device__ __nv_bfloat16 g_Ahi[(size_t)TT * BB * 1024];
static __device__ __nv_bfloat16 g_Alo[(size_t)TT * BB * 1024];
static __device__ __nv_bfloat16 g_Whi[(size_t)GG * 1024];
static __device__ __nv_bfloat16 g_Wlo[(size_t)GG * 1024];
static __device__ unsigned char g_Wh8[(size_t)GG * 1024];    // e4m3(W_hi)
static __device__ unsigned char g_Wl8[(size_t)GG * 1024];    // e4m3(512 * W_lo)
static __device__ __nv_bfloat16 g_ghi[2][BB * HH];           // h hi bf16, ping-pong [b][k]
static __device__ __nv_bfloat16 g_glo[2][BB * HH];           // h lo bf16 (kept for L0->L1 A feed)
static __device__ unsigned char g_gh8[2][BB * HH];           // e4m3(h_hi)
static __device__ unsigned char g_gl8[2][BB * HH];           // e4m3(512 * h_lo)

// ---------------- PTX helpers ----------------
__device__ __forceinline__ uint32_t smem_u32(const void* p) {
    uint32_t a;
    asm("{ .reg .u64 t; cvta.to.shared.u64 t, %1; cvt.u32.u64 %0, t; }" : "=r"(a) : "l"(p));
    return a;
}
__device__ __forceinline__ void cp_async16(uint32_t dst, const void* src) {
    asm volatile("cp.async.cg.shared.global [%0], [%1], 16;" :: "r"(dst), "l"(src));
}
__device__ __forceinline__ void cp_commit() { asm volatile("cp.async.commit_group;" ::: "memory"); }
template<int N> __device__ __forceinline__ void cp_wait() { asm volatile("cp.async.wait_group %0;" :: "n"(N) : "memory"); }

#define LDSM4(r, addr) \
    asm volatile("ldmatrix.sync.aligned.m8n8.x4.shared.b16 {%0,%1,%2,%3}, [%4];" \
        : "=r"((r)[0]), "=r"((r)[1]), "=r"((r)[2]), "=r"((r)[3]) : "r"(addr))

#define MMA16816(c, a, b) \
    asm volatile("mma.sync.aligned.m16n8k16.row.col.f32.bf16.bf16.f32 " \
        "{%0,%1,%2,%3}, {%4,%5,%6,%7}, {%8,%9}, {%0,%1,%2,%3};" \
        : "+f"((c)[0]), "+f"((c)[1]), "+f"((c)[2]), "+f"((c)[3]) \
        : "r"((a)[0]), "r"((a)[1]), "r"((a)[2]), "r"((a)[3]), "r"((b)[0]), "r"((b)[1]))

#define MMAF8(c, a, b) \
    asm volatile("mma.sync.aligned.m16n8k32.row.col.f32.e4m3.e4m3.f32 " \
        "{%0,%1,%2,%3}, {%4,%5,%6,%7}, {%8,%9}, {%0,%1,%2,%3};" \
        : "+f"((c)[0]), "+f"((c)[1]), "+f"((c)[2]), "+f"((c)[3]) \
        : "r"((a)[0]), "r"((a)[1]), "r"((a)[2]), "r"((a)[3]), "r"((b)[0]), "r"((b)[1]))

__device__ __forceinline__ unsigned char to_e4m3(float v) {
    return (unsigned char)__nv_cvt_float_to_fp8(v, __NV_SATFINITE, __NV_E4M3);
}

// ---------------- fp32 -> split conversion ----------------
// mode 0: W [G][K] -> bf16 hi/lo + fp8 (hi, 512*lo), zero-padded to 1024
// mode 1: x [B][T][DIN], row m=t*B+b -> A bf16 hi/lo [32768][1024]
__global__ void conv_split(const float* __restrict__ src, int K, int mode) {
    size_t i = (size_t)blockIdx.x * blockDim.x + threadIdx.x;
    size_t total = (mode == 0) ? ((size_t)GG << 10) : ((size_t)TT * BB << 10);
    if (i >= total) return;
    int k = (int)(i & 1023);
    size_t row = i >> 10;
    float v = 0.f;
    if (k < K) {
        if (mode == 1) {
            int t = (int)(row >> 6), b = (int)(row & 63);
            v = src[((size_t)b * TT + t) * DIN + k];
        } else {
            v = src[row * K + k];
        }
    }
    __nv_bfloat16 h = __float2bfloat16(v);
    float hf = __bfloat162float(h);
    float lf = v - hf;
    if (mode == 0) {
        g_Whi[i] = h; g_Wlo[i] = __float2bfloat16(lf);
        g_Wh8[i] = to_e4m3(hf);
        g_Wl8[i] = to_e4m3(lf * 512.0f);
    } else {
        g_Ahi[i] = h; g_Alo[i] = __float2bfloat16(lf);
    }
}

// ---------------- mma.sync bf16 split GEMM (round-9, passing) ----------------
#define TROW 144
#define TILE_B (128 * TROW)
#define STAGE_B (4 * TILE_B)
#define GEMM_SMEM (2 * STAGE_B + 512)

__device__ __forceinline__ void gemm_issue_loads(uint32_t sbase, int c, int m0, int n0, int tid) {
    const __nv_bfloat16* ptrs[4] = { g_Ahi, g_Alo, g_Whi, g_Wlo };
#pragma unroll
    for (int q = 0; q < 4; q++) {
        const __nv_bfloat16* p = ptrs[q];
        int rowbase = (q < 2) ? m0 : n0;
        uint32_t tb = sbase + q * TILE_B;
#pragma unroll
        for (int i = 0; i < 4; i++) {
            int idx = tid + i * 256;
            int r = idx >> 3, s = idx & 7;
            cp_async16(tb + r * TROW + s * 16,
                       p + (((size_t)(rowbase + r)) << 10) + (c << 6) + (s << 3));
        }
    }
}

__global__ void __launch_bounds__(256, 1)
gemm_bf16_split(const float* __restrict__ b1, const float* __restrict__ b2, int nch)
{
    extern __shared__ char smraw[];
    uint32_t sbase = smem_u32(smraw);
    float* sbias = (float*)(smraw + 2 * STAGE_B);

    const int tid = threadIdx.x;
    const int lane = tid & 31, wid = tid >> 5;
    const int n0 = blockIdx.x * 128;
    const int m0 = blockIdx.y * 128;
    const int wm = (wid >> 2) * 64;
    const int wn = (wid & 3) * 32;

    if (tid < 128) sbias[tid] = b1[n0 + tid] + b2[n0 + tid];

    float acc[4][4][4];
#pragma unroll
    for (int i = 0; i < 4; i++)
#pragma unroll
        for (int j = 0; j < 4; j++)
#pragma unroll
            for (int q = 0; q < 4; q++) acc[i][j][q] = 0.f;

    gemm_issue_loads(sbase, 0, m0, n0, tid);
    cp_commit();

    const uint32_t a_row = wm + (lane & 15);
    const uint32_t a_coh = (lane >> 4) << 4;
    const uint32_t b_rlo = (lane >> 4) * 8 + (lane & 7);
    const uint32_t b_coh = ((lane >> 3) & 1) << 4;

    for (int c = 0; c < nch; c++) {
        if (c < nch - 1) {
            gemm_issue_loads(sbase + ((c + 1) & 1) * STAGE_B, c + 1, m0, n0, tid);
            cp_commit();
            cp_wait<1>();
        } else {
            cp_wait<0>();
        }
        __syncthreads();

        const uint32_t buf = sbase + (c & 1) * STAGE_B;
        const uint32_t Ahi_b = buf;
        const uint32_t Alo_b = buf + TILE_B;
        const uint32_t Whi_b = buf + 2 * TILE_B;
        const uint32_t Wlo_b = buf + 3 * TILE_B;

#pragma unroll
        for (int ks = 0; ks < 4; ks++) {
            const uint32_t kso = ks * 32;
            uint32_t ah[4][4], bh[4][2];
#pragma unroll
            for (int mt = 0; mt < 4; mt++)
                LDSM4(ah[mt], Ahi_b + (a_row + mt * 16) * TROW + kso + a_coh);
#pragma unroll
            for (int g = 0; g < 2; g++) {
                uint32_t t4[4];
                LDSM4(t4, Whi_b + (wn + g * 16 + b_rlo) * TROW + kso + b_coh);
                bh[g * 2][0] = t4[0]; bh[g * 2][1] = t4[1];
                bh[g * 2 + 1][0] = t4[2]; bh[g * 2 + 1][1] = t4[3];
            }
#pragma unroll
            for (int mt = 0; mt < 4; mt++)
#pragma unroll
                for (int nt = 0; nt < 4; nt++)
                    MMA16816(acc[mt][nt], ah[mt], bh[nt]);

            uint32_t bl[4][2];
#pragma unroll
            for (int g = 0; g < 2; g++) {
                uint32_t t4[4];
                LDSM4(t4, Wlo_b + (wn + g * 16 + b_rlo) * TROW + kso + b_coh);
                bl[g * 2][0] = t4[0]; bl[g * 2][1] = t4[1];
                bl[g * 2 + 1][0] = t4[2]; bl[g * 2 + 1][1] = t4[3];
            }
#pragma unroll
            for (int mt = 0; mt < 4; mt++)
#pragma unroll
                for (int nt = 0; nt < 4; nt++)
                    MMA16816(acc[mt][nt], ah[mt], bl[nt]);

            uint32_t al[4][4];
#pragma unroll
            for (int mt = 0; mt < 4; mt++)
                LDSM4(al[mt], Alo_b + (a_row + mt * 16) * TROW + kso + a_coh);
#pragma unroll
            for (int mt = 0; mt < 4; mt++)
#pragma unroll
                for (int nt = 0; nt < 4; nt++)
                    MMA16816(acc[mt][nt], al[mt], bh[nt]);
        }
        __syncthreads();
    }

    const int r_lo = lane >> 2;
    const int cpos = (lane & 3) * 2;
#pragma unroll
    for (int mt = 0; mt < 4; mt++) {
        int row0 = m0 + wm + mt * 16 + r_lo;
#pragma unroll
        for (int nt = 0; nt < 4; nt++) {
            int cl = wn + nt * 8 + cpos;
            float bx = sbias[cl], by = sbias[cl + 1];
            float2 v0 = make_float2(acc[mt][nt][0] + bx, acc[mt][nt][1] + by);
            float2 v1 = make_float2(acc[mt][nt][2] + bx, acc[mt][nt][3] + by);
            *(float2*)&g_xg[(size_t)row0 * GG + n0 + cl] = v0;
            *(float2*)&g_xg[(size_t)(row0 + 8) * GG + n0 + cl] = v1;
        }
    }
}

// ---------------- tensor-core persistent recurrence: bf16 main + fp8 corrections ----------------
// Per warp per step: main pass hh*Wh (bf16 k16, 256 MMA) + corrections
// (512*hl)*Wh8 + hh8*(512*Wl) (fp8 k32, 256 MMA), corr folded back with 2^-9.
#define WROW 2064
#define WS_B (32 * WROW)               // 66048 (Whi bf16)
#define W8ROW 1040
#define W8_B (32 * W8ROW)              // 33280 each (Wh8, Wl8)
#define RROW 144
#define HHTILE (16 * RROW)             // 2304 (hh bf16)
#define H8ROW 80
#define H8TILE (16 * H8ROW)            // 1280 each (hh8, hl8)
#define RSTG_B (HHTILE + 2 * H8TILE)   // 4864
#define NBUF 4
#define WARP_STG (NBUF * RSTG_B)       // 19456
#define REC_SMEM (WS_B + 2 * W8_B + 4 * WARP_STG)   // 210432

__global__ void zero_rec() {
    int i = blockIdx.x * blockDim.x + threadIdx.x;
    if (i == 0) { g_gen = 0u; g_cnt = 0u; }
    uint32_t* p1 = (uint32_t*)g_ghi;
    uint32_t* p2 = (uint32_t*)g_glo;
    for (int k = i; k < 65536; k += gridDim.x * blockDim.x) { p1[k] = 0u; p2[k] = 0u; }
    uint32_t* p3 = (uint32_t*)g_gh8;
    uint32_t* p4 = (uint32_t*)g_gl8;
    for (int k = i; k < 32768; k += gridDim.x * blockDim.x) { p3[k] = 0u; p4[k] = 0u; }
}

// stage one 64-k chunk for this warp's 16 batch rows: hh bf16 + hh8 + hl8 fp8
__device__ __forceinline__ void rec_stage_w(uint32_t dst, const __nv_bfloat16* ghi,
                                            const unsigned char* gh8, const unsigned char* gl8,
                                            int wid, int c, int lane) {
#pragma unroll
    for (int i = 0; i < 4; i++) {
        int idx = lane + i * 32;
        int r = idx >> 3, s = idx & 7;
        cp_async16(dst + r * RROW + s * 16,
                   ghi + (size_t)(wid * 16 + r) * HH + c * 64 + s * 8);
    }
#pragma unroll
    for (int i = 0; i < 2; i++) {
        int idx = lane + i * 32;
        int r = idx >> 2, s = idx & 3;
        size_t so = (size_t)(wid * 16 + r) * HH + c * 64 + s * 16;
        cp_async16(dst + HHTILE + r * H8ROW + s * 16, gh8 + so);
        cp_async16(dst + HHTILE + H8TILE + r * H8ROW + s * 16, gl8 + so);
    }
    cp_commit();
}

template<int LAYER>
__global__ void __launch_bounds__(128, 1)
lstm_rec_tc(float* __restrict__ out_ext)
{
    extern __shared__ char smraw[];
    const uint32_t sb = smem_u32(smraw);
    const uint32_t ws_hi = sb;
    const uint32_t ws8h  = sb + WS_B;
    const uint32_t ws8l  = sb + WS_B + W8_B;

    const int tid = threadIdx.x;
    const int lane = tid & 31, wid = tid >> 5;
    const int j0 = blockIdx.x * 8;
    const uint32_t wstg = sb + WS_B + 2 * W8_B + wid * WARP_STG;

    // Load W tiles (32 gate rows) into smem once: Whi bf16 + Wh8 + Wl8 fp8
#pragma unroll 4
    for (int n = 0; n < 32; n++) {
        int grow = ((n >> 3) << 10) + j0 + (n & 7);
        cp_async16(ws_hi + n * WROW + tid * 16, g_Whi + ((size_t)grow << 10) + tid * 8);
        if (tid < 64) {
            cp_async16(ws8h + n * W8ROW + tid * 16, g_Wh8 + ((size_t)grow << 10) + tid * 16);
            cp_async16(ws8l + n * W8ROW + tid * 16, g_Wl8 + ((size_t)grow << 10) + tid * 16);
        }
    }
    cp_commit(); cp_wait<0>();
    __syncthreads();

    const uint32_t a_off  = (lane & 15) * RROW + ((lane >> 4) << 4);
    const uint32_t a8_off = (lane & 15) * H8ROW + ((lane >> 4) << 4);
    const uint32_t w_off  = ((lane >> 4) * 8 + (lane & 7)) * WROW + (((lane >> 3) & 1) << 4);
    const uint32_t w8_off = ((lane >> 4) * 8 + (lane & 7)) * W8ROW + (((lane >> 3) & 1) << 4);

    // cell mapping: acc[nt][0]=(r0,c0) [1]=(r0,c1) [2]=(r0+8,c0) [3]=(r0+8,c1); gate=nt
    const int r0 = lane >> 2;
    const int c0 = (lane & 3) * 2;
    const int bA = wid * 16 + r0;
    const int bB = bA + 8;
    const int jj = j0 + c0;

    float cst[4] = {0.f, 0.f, 0.f, 0.f};
    unsigned gen = 0;

    for (int t = 0; t < TT; t++) {
        const __nv_bfloat16* ghi_in = g_ghi[t & 1];
        const unsigned char* gh8_in = g_gh8[t & 1];
        const unsigned char* gl8_in = g_gl8[t & 1];
        __nv_bfloat16* ghi_out = g_ghi[(t + 1) & 1];
        unsigned char* gh8_out = g_gh8[(t + 1) & 1];
        unsigned char* gl8_out = g_gl8[(t + 1) & 1];

        float2 xgv[2][4];
#pragma unroll
        for (int rp = 0; rp < 2; rp++) {
            size_t base = ((size_t)t * BB + (rp ? bB : bA)) * GG + jj;
#pragma unroll
            for (int g = 0; g < 4; g++)
                xgv[rp][g] = *(const float2*)&g_xg[base + (size_t)g * HH];
        }

        float acc[4][4], cor[4][4];
#pragma unroll
        for (int nt = 0; nt < 4; nt++)
#pragma unroll
            for (int q = 0; q < 4; q++) { acc[nt][q] = 0.f; cor[nt][q] = 0.f; }

        rec_stage_w(wstg + 0 * RSTG_B, ghi_in, gh8_in, gl8_in, wid, 0, lane);
        rec_stage_w(wstg + 1 * RSTG_B, ghi_in, gh8_in, gl8_in, wid, 1, lane);
        rec_stage_w(wstg + 2 * RSTG_B, ghi_in, gh8_in, gl8_in, wid, 2, lane);

        for (int c = 0; c < 16; c++) {
            if (c < 13) {
                rec_stage_w(wstg + ((c + 3) & 3) * RSTG_B, ghi_in, gh8_in, gl8_in, wid, c + 3, lane);
                cp_wait<3>();
            } else if (c == 13) cp_wait<2>();
            else if (c == 14) cp_wait<1>();
            else cp_wait<0>();
            __syncwarp();

            const uint32_t hhb = wstg + (c & 3) * RSTG_B;
            const uint32_t h8b = hhb + HHTILE;

#pragma unroll
            for (int kl2 = 0; kl2 < 2; kl2++) {
                // ---- bf16 main pass: two k16 steps ----
#pragma unroll
                for (int klh = 0; klh < 2; klh++) {
                    const int kl = kl2 * 2 + klh;
                    const uint32_t kby = (uint32_t)(c * 64 + kl * 16) * 2;
                    uint32_t ah[4], bh[4][2];
                    LDSM4(ah, hhb + a_off + kl * 32);
                    {
                        uint32_t t4[4];
                        LDSM4(t4, ws_hi + w_off + kby);
                        bh[0][0] = t4[0]; bh[0][1] = t4[1]; bh[1][0] = t4[2]; bh[1][1] = t4[3];
                        LDSM4(t4, ws_hi + 16 * WROW + w_off + kby);
                        bh[2][0] = t4[0]; bh[2][1] = t4[1]; bh[3][0] = t4[2]; bh[3][1] = t4[3];
                    }
#pragma unroll
                    for (int nt = 0; nt < 4; nt++)
                        MMA16816(acc[nt], ah, bh[nt]);
                }
                // ---- fp8 correction pass: one k32 step ----
                {
                    const uint32_t kc8 = (uint32_t)(c * 64 + kl2 * 32);
                    uint32_t a8h[4], a8l[4], b8h[4][2], b8l[4][2];
                    LDSM4(a8h, h8b + a8_off + kl2 * 32);
                    LDSM4(a8l, h8b + H8TILE + a8_off + kl2 * 32);
                    {
                        uint32_t t4[4];
                        LDSM4(t4, ws8h + w8_off + kc8);
                        b8h[0][0] = t4[0]; b8h[0][1] = t4[1]; b8h[1][0] = t4[2]; b8h[1][1] = t4[3];
                        LDSM4(t4, ws8h + 16 * W8ROW + w8_off + kc8);
                        b8h[2][0] = t4[0]; b8h[2][1] = t4[1]; b8h[3][0] = t4[2]; b8h[3][1] = t4[3];
                        LDSM4(t4, ws8l + w8_off + kc8);
                        b8l[0][0] = t4[0]; b8l[0][1] = t4[1]; b8l[1][0] = t4[2]; b8l[1][1] = t4[3];
                        LDSM4(t4, ws8l + 16 * W8ROW + w8_off + kc8);
                        b8l[2][0] = t4[0]; b8l[2][1] = t4[1]; b8l[3][0] = t4[2]; b8l[3][1] = t4[3];
                    }
#pragma unroll
                    for (int nt = 0; nt < 4; nt++) {
                        MMAF8(cor[nt], a8l, b8h[nt]);   // (512*hl) * Wh8
                        MMAF8(cor[nt], a8h, b8l[nt]);   // hh8 * (512*Wl)
                    }
                }
            }
        }

        // pointwise LSTM update (thread-local cells); corrections folded with 2^-9
#pragma unroll
        for (int rp = 0; rp < 2; rp++) {
            const int b = rp ? bB : bA;
            float hn[2], hif[2], hlf[2];
#pragma unroll
            for (int cc = 0; cc < 2; cc++) {
                const int q = rp * 2 + cc;
                float pi = acc[0][q] + cor[0][q] * 0.001953125f + (cc ? xgv[rp][0].y : xgv[rp][0].x);
                float pf = acc[1][q] + cor[1][q] * 0.001953125f + (cc ? xgv[rp][1].y : xgv[rp][1].x);
                float pg = acc[2][q] + cor[2][q] * 0.001953125f + (cc ? xgv[rp][2].y : xgv[rp][2].x);
                float po = acc[3][q] + cor[3][q] * 0.001953125f + (cc ? xgv[rp][3].y : xgv[rp][3].x);
                float ig = 1.f / (1.f + expf(-pi));
                float fg = 1.f / (1.f + expf(-pf));
                float gc = tanhf(pg);
                float og = 1.f / (1.f + expf(-po));
                float cn = fg * cst[q] + ig * gc;
                cst[q] = cn;
                hn[cc] = og * tanhf(cn);
            }
            __nv_bfloat16 h0 = __float2bfloat16(hn[0]);
            __nv_bfloat16 h1 = __float2bfloat16(hn[1]);
            hif[0] = __bfloat162float(h0); hif[1] = __bfloat162float(h1);
            hlf[0] = hn[0] - hif[0];       hlf[1] = hn[1] - hif[1];
            __nv_bfloat16 l0 = __float2bfloat16(hlf[0]);
            __nv_bfloat16 l1 = __float2bfloat16(hlf[1]);
            size_t hoff = (size_t)b * HH + jj;
            *(__nv_bfloat162*)&ghi_out[hoff] = __nv_bfloat162(h0, h1);
            unsigned short p8h = (unsigned short)to_e4m3(hif[0]) |
                                 ((unsigned short)to_e4m3(hif[1]) << 8);
            unsigned short p8l = (unsigned short)to_e4m3(hlf[0] * 512.0f) |
                                 ((unsigned short)to_e4m3(hlf[1] * 512.0f) << 8);
            *(unsigned short*)&gh8_out[hoff] = p8h;
            *(unsigned short*)&gl8_out[hoff] = p8l;
            if (LAYER == 0) {
                // feed layer-1 GEMM directly: A row = t*B + b, bf16 hi/lo
                size_t arow = (((size_t)t * BB + b) << 10) + jj;
                *(__nv_bfloat162*)&g_Ahi[arow] = __nv_bfloat162(h0, h1);
                *(__nv_bfloat162*)&g_Alo[arow] = __nv_bfloat162(l0, l1);
            } else {
                *(float2*)&out_ext[((size_t)b * TT + t) * HH + jj] = make_float2(hn[0], hn[1]);
            }
        }

        // ---- grid barrier (round-6/9 atomic version, proven) ----
        __threadfence();
        __syncthreads();
        gen++;
        if (tid == 0) {
            if (atomicAdd(&g_cnt, 1u) == NCTA - 1) {
                g_cnt = 0u;
                __threadfence();
                *(volatile unsigned*)&g_gen = gen;
            } else {
                while (*(volatile unsigned*)&g_gen < gen) { }
                __threadfence();
            }
        }
        __syncthreads();
    }
}

// ---------------- launch ----------------
extern "C" void kernel_launch(void* const* d_in, const int* in_sizes, int n_in,
                              void* d_out, int out_size)
{
    (void)in_sizes; (void)n_in; (void)out_size;
    const float* x     = (const float*)d_in[0];
    const float* W_ih0 = (const float*)d_in[1];
    const float* W_hh0 = (const float*)d_in[2];
    const float* b_ih0 = (const float*)d_in[3];
    const float* b_hh0 = (const float*)d_in[4];
    const float* W_ih1 = (const float*)d_in[5];
    const float* W_hh1 = (const float*)d_in[6];
    const float* b_ih1 = (const float*)d_in[7];
    const float* b_hh1 = (const float*)d_in[8];
    float* out = (float*)d_out;

    cudaFuncSetAttribute(gemm_bf16_split, cudaFuncAttributeMaxDynamicSharedMemorySize, GEMM_SMEM);
    cudaFuncSetAttribute(lstm_rec_tc<0>, cudaFuncAttributeMaxDynamicSharedMemorySize, REC_SMEM);
    cudaFuncSetAttribute(lstm_rec_tc<1>, cudaFuncAttributeMaxDynamicSharedMemorySize, REC_SMEM);

    const size_t convW_n = (size_t)GG * 1024;
    const size_t convA_n = (size_t)TT * BB * 1024;
    dim3 gemm_grid(GG / 128, (TT * BB) / 128);
    const int nch0 = (DIN + 63) / 64;   // 14 chunks cover k<896; rest is zero padding
    const int nch1 = 16;

    // ---- Layer 0 ----
    conv_split<<<(int)((convW_n + 255) / 256), 256>>>(W_ih0, DIN, 0);
    conv_split<<<(int)((convA_n + 255) / 256), 256>>>(x, DIN, 1);
    gemm_bf16_split<<<gemm_grid, 256, GEMM_SMEM>>>(b_ih0, b_hh0, nch0);
    conv_split<<<(int)((convW_n + 255) / 256), 256>>>(W_hh0, HH, 0);
    zero_rec<<<256, 256>>>();
    lstm_rec_tc<0><<<NCTA, 128, REC_SMEM>>>(out);   // also writes g_Ahi/g_Alo for layer 1

    // ---- Layer 1 ----
    conv_split<<<(int)((convW_n + 255) / 256), 256>>>(W_ih1, HH, 0);
    gemm_bf16_split<<<gemm_grid, 256, GEMM_SMEM>>>(b_ih1, b_hh1, nch1);
    conv_split<<<(int)((convW_n + 255) / 256), 256>>>(W_hh1, HH, 0);
    zero_rec<<<256, 256>>>();
    lstm_rec_tc<1><<<NCTA, 128, REC_SMEM>>>(out);
}

// round 11
// speedup vs baseline: 1.0968x; 1.0968x over previous
#include <cuda_runtime.h>
#include <cuda_bf16.h>
#include <math.h>
#include <stdint.h>

#define BB 64
#define TT 512
#define DIN 862
#define HH 1024
#define GG 4096

#define NCTA 128

// ---------------- scratch (allocation-free rule: __device__ globals) ----------------
static __device__ float g_xg[(size_t)TT * BB * GG];          // [T*B][G] gate preactivations
static __device__ unsigned g_gen;
static __device__ unsigned g_cnt;
static __device__ __nv_bfloat16 g_Ahi[(size_t)TT * BB * 1024];
static __device__ __nv_bfloat16 g_Alo[(size_t)TT * BB * 1024];
static __device__ __nv_bfloat16 g_Whi[(size_t)GG * 1024];    // input-GEMM weights
static __device__ __nv_bfloat16 g_Wlo[(size_t)GG * 1024];
static __device__ __nv_bfloat16 g_Rhi[(size_t)GG * 1024];    // recurrent weights (separate!)
static __device__ __nv_bfloat16 g_Rlo[(size_t)GG * 1024];
static __device__ __nv_bfloat16 g_ghi[2][BB * HH];           // h state bf16 hi, ping-pong [b][k]
static __device__ __nv_bfloat16 g_glo[2][BB * HH];           // h state bf16 lo

// ---------------- PTX helpers ----------------
__device__ __forceinline__ uint32_t smem_u32(const void* p) {
    uint32_t a;
    asm("{ .reg .u64 t; cvta.to.shared.u64 t, %1; cvt.u32.u64 %0, t; }" : "=r"(a) : "l"(p));
    return a;
}
__device__ __forceinline__ void cp_async16(uint32_t dst, const void* src) {
    asm volatile("cp.async.cg.shared.global [%0], [%1], 16;" :: "r"(dst), "l"(src));
}
__device__ __forceinline__ void cp_commit() { asm volatile("cp.async.commit_group;" ::: "memory"); }
template<int N> __device__ __forceinline__ void cp_wait() { asm volatile("cp.async.wait_group %0;" :: "n"(N) : "memory"); }

#define LDSM4(r, addr) \
    asm volatile("ldmatrix.sync.aligned.m8n8.x4.shared.b16 {%0,%1,%2,%3}, [%4];" \
        : "=r"((r)[0]), "=r"((r)[1]), "=r"((r)[2]), "=r"((r)[3]) : "r"(addr))

#define MMA16816(c, a, b) \
    asm volatile("mma.sync.aligned.m16n8k16.row.col.f32.bf16.bf16.f32 " \
        "{%0,%1,%2,%3}, {%4,%5,%6,%7}, {%8,%9}, {%0,%1,%2,%3};" \
        : "+f"((c)[0]), "+f"((c)[1]), "+f"((c)[2]), "+f"((c)[3]) \
        : "r"((a)[0]), "r"((a)[1]), "r"((a)[2]), "r"((a)[3]), "r"((b)[0]), "r"((b)[1]))

// ---------------- fp32 -> split bf16 conversions ----------------
// W_ih [G][K] -> g_Whi/g_Wlo [G][1024], zero-padded
__global__ void convW(const float* __restrict__ src, int K) {
    size_t i = (size_t)blockIdx.x * blockDim.x + threadIdx.x;
    if (i >= ((size_t)GG << 10)) return;
    int k = (int)(i & 1023);
    size_t row = i >> 10;
    float v = (k < K) ? src[row * K + k] : 0.f;
    __nv_bfloat16 h = __float2bfloat16(v);
    g_Whi[i] = h;
    g_Wlo[i] = __float2bfloat16(v - __bfloat162float(h));
}

// Fused: W_hh -> g_Rhi/g_Rlo, zero h-state + barrier slots, and (layer 0) x -> g_Ahi/g_Alo
#define NWELEM ((size_t)GG << 10)        // 4194304
#define NZ 131072                        // u32 words: g_ghi (65536) + g_glo (65536)
#define NAELEM ((size_t)TT * BB << 10)   // 33554432
__global__ void conv_all(const float* __restrict__ x, const float* __restrict__ Whh, int has_x) {
    size_t i = (size_t)blockIdx.x * blockDim.x + threadIdx.x;
    if (i < NWELEM) {
        int k = (int)(i & 1023);
        size_t row = i >> 10;
        float v = Whh[(row << 10) + k];
        __nv_bfloat16 h = __float2bfloat16(v);
        g_Rhi[i] = h;
        g_Rlo[i] = __float2bfloat16(v - __bfloat162float(h));
    } else if (i < NWELEM + NZ) {
        size_t z = i - NWELEM;
        if (z == 0) { g_gen = 0u; g_cnt = 0u; }
        if (z < 65536) ((uint32_t*)g_ghi)[z] = 0u;
        else           ((uint32_t*)g_glo)[z - 65536] = 0u;
    } else if (has_x) {
        size_t j = i - NWELEM - NZ;
        if (j < NAELEM) {
            int k = (int)(j & 1023);
            size_t row = j >> 10;
            int t = (int)(row >> 6), b = (int)(row & 63);
            float v = (k < DIN) ? x[((size_t)b * TT + t) * DIN + k] : 0.f;
            __nv_bfloat16 h = __float2bfloat16(v);
            g_Ahi[j] = h;
            g_Alo[j] = __float2bfloat16(v - __bfloat162float(h));
        }
    }
}

// ---------------- mma.sync bf16 split GEMM (round-9, passing) ----------------
#define TROW 144
#define TILE_B (128 * TROW)
#define STAGE_B (4 * TILE_B)
#define GEMM_SMEM (2 * STAGE_B + 512)

__device__ __forceinline__ void gemm_issue_loads(uint32_t sbase, int c, int m0, int n0, int tid) {
    const __nv_bfloat16* ptrs[4] = { g_Ahi, g_Alo, g_Whi, g_Wlo };
#pragma unroll
    for (int q = 0; q < 4; q++) {
        const __nv_bfloat16* p = ptrs[q];
        int rowbase = (q < 2) ? m0 : n0;
        uint32_t tb = sbase + q * TILE_B;
#pragma unroll
        for (int i = 0; i < 4; i++) {
            int idx = tid + i * 256;
            int r = idx >> 3, s = idx & 7;
            cp_async16(tb + r * TROW + s * 16,
                       p + (((size_t)(rowbase + r)) << 10) + (c << 6) + (s << 3));
        }
    }
}

__global__ void __launch_bounds__(256, 1)
gemm_bf16_split(const float* __restrict__ b1, const float* __restrict__ b2, int nch)
{
    extern __shared__ char smraw[];
    uint32_t sbase = smem_u32(smraw);
    float* sbias = (float*)(smraw + 2 * STAGE_B);

    const int tid = threadIdx.x;
    const int lane = tid & 31, wid = tid >> 5;
    const int n0 = blockIdx.x * 128;
    const int m0 = blockIdx.y * 128;
    const int wm = (wid >> 2) * 64;
    const int wn = (wid & 3) * 32;

    if (tid < 128) sbias[tid] = b1[n0 + tid] + b2[n0 + tid];

    float acc[4][4][4];
#pragma unroll
    for (int i = 0; i < 4; i++)
#pragma unroll
        for (int j = 0; j < 4; j++)
#pragma unroll
            for (int q = 0; q < 4; q++) acc[i][j][q] = 0.f;

    gemm_issue_loads(sbase, 0, m0, n0, tid);
    cp_commit();

    const uint32_t a_row = wm + (lane & 15);
    const uint32_t a_coh = (lane >> 4) << 4;
    const uint32_t b_rlo = (lane >> 4) * 8 + (lane & 7);
    const uint32_t b_coh = ((lane >> 3) & 1) << 4;

    for (int c = 0; c < nch; c++) {
        if (c < nch - 1) {
            gemm_issue_loads(sbase + ((c + 1) & 1) * STAGE_B, c + 1, m0, n0, tid);
            cp_commit();
            cp_wait<1>();
        } else {
            cp_wait<0>();
        }
        __syncthreads();

        const uint32_t buf = sbase + (c & 1) * STAGE_B;
        const uint32_t Ahi_b = buf;
        const uint32_t Alo_b = buf + TILE_B;
        const uint32_t Whi_b = buf + 2 * TILE_B;
        const uint32_t Wlo_b = buf + 3 * TILE_B;

#pragma unroll
        for (int ks = 0; ks < 4; ks++) {
            const uint32_t kso = ks * 32;
            uint32_t ah[4][4], bh[4][2];
#pragma unroll
            for (int mt = 0; mt < 4; mt++)
                LDSM4(ah[mt], Ahi_b + (a_row + mt * 16) * TROW + kso + a_coh);
#pragma unroll
            for (int g = 0; g < 2; g++) {
                uint32_t t4[4];
                LDSM4(t4, Whi_b + (wn + g * 16 + b_rlo) * TROW + kso + b_coh);
                bh[g * 2][0] = t4[0]; bh[g * 2][1] = t4[1];
                bh[g * 2 + 1][0] = t4[2]; bh[g * 2 + 1][1] = t4[3];
            }
#pragma unroll
            for (int mt = 0; mt < 4; mt++)
#pragma unroll
                for (int nt = 0; nt < 4; nt++)
                    MMA16816(acc[mt][nt], ah[mt], bh[nt]);

            uint32_t bl[4][2];
#pragma unroll
            for (int g = 0; g < 2; g++) {
                uint32_t t4[4];
                LDSM4(t4, Wlo_b + (wn + g * 16 + b_rlo) * TROW + kso + b_coh);
                bl[g * 2][0] = t4[0]; bl[g * 2][1] = t4[1];
                bl[g * 2 + 1][0] = t4[2]; bl[g * 2 + 1][1] = t4[3];
            }
#pragma unroll
            for (int mt = 0; mt < 4; mt++)
#pragma unroll
                for (int nt = 0; nt < 4; nt++)
                    MMA16816(acc[mt][nt], ah[mt], bl[nt]);

            uint32_t al[4][4];
#pragma unroll
            for (int mt = 0; mt < 4; mt++)
                LDSM4(al[mt], Alo_b + (a_row + mt * 16) * TROW + kso + a_coh);
#pragma unroll
            for (int mt = 0; mt < 4; mt++)
#pragma unroll
                for (int nt = 0; nt < 4; nt++)
                    MMA16816(acc[mt][nt], al[mt], bh[nt]);
        }
        __syncthreads();
    }

    const int r_lo = lane >> 2;
    const int cpos = (lane & 3) * 2;
#pragma unroll
    for (int mt = 0; mt < 4; mt++) {
        int row0 = m0 + wm + mt * 16 + r_lo;
#pragma unroll
        for (int nt = 0; nt < 4; nt++) {
            int cl = wn + nt * 8 + cpos;
            float bx = sbias[cl], by = sbias[cl + 1];
            float2 v0 = make_float2(acc[mt][nt][0] + bx, acc[mt][nt][1] + by);
            float2 v1 = make_float2(acc[mt][nt][2] + bx, acc[mt][nt][3] + by);
            *(float2*)&g_xg[(size_t)row0 * GG + n0 + cl] = v0;
            *(float2*)&g_xg[(size_t)(row0 + 8) * GG + n0 + cl] = v1;
        }
    }
}

// ---------------- tensor-core persistent recurrence (round-9 structure, R weights) ----------------
#define WROW 2064
#define WS_B (32 * WROW)
#define RROW 144
#define RBUF_B (16 * RROW)
#define RSTG_B (2 * RBUF_B)
#define NBUF 4
#define WARP_STG (NBUF * RSTG_B)
#define REC_SMEM (2 * WS_B + 4 * WARP_STG)

__device__ __forceinline__ void rec_stage_w(uint32_t dst, const __nv_bfloat16* ghi,
                                            const __nv_bfloat16* glo, int wid, int c, int lane) {
#pragma unroll
    for (int i = 0; i < 4; i++) {
        int idx = lane + i * 32;
        int r = idx >> 3, s = idx & 7;
        uint32_t d = dst + r * RROW + s * 16;
        size_t so = (size_t)(wid * 16 + r) * 1024 + c * 64 + s * 8;
        cp_async16(d, ghi + so);
        cp_async16(d + RBUF_B, glo + so);
    }
    cp_commit();
}

template<int LAYER>
__global__ void __launch_bounds__(128, 1)
lstm_rec_tc(float* __restrict__ out_ext)
{
    extern __shared__ char smraw[];
    const uint32_t sb = smem_u32(smraw);
    const uint32_t ws_hi = sb;
    const uint32_t ws_lo = sb + WS_B;

    const int tid = threadIdx.x;
    const int lane = tid & 31, wid = tid >> 5;
    const int j0 = blockIdx.x * 8;
    const uint32_t wstg = sb + 2 * WS_B + wid * WARP_STG;

#pragma unroll 4
    for (int n = 0; n < 32; n++) {
        int grow = ((n >> 3) << 10) + j0 + (n & 7);
        cp_async16(ws_hi + n * WROW + tid * 16, g_Rhi + ((size_t)grow << 10) + tid * 8);
        cp_async16(ws_lo + n * WROW + tid * 16, g_Rlo + ((size_t)grow << 10) + tid * 8);
    }
    cp_commit(); cp_wait<0>();
    __syncthreads();

    const uint32_t a_off = (lane & 15) * RROW + ((lane >> 4) << 4);
    const uint32_t w_off = ((lane >> 4) * 8 + (lane & 7)) * WROW + (((lane >> 3) & 1) << 4);

    const int r0 = lane >> 2;
    const int c0 = (lane & 3) * 2;
    const int bA = wid * 16 + r0;
    const int bB = bA + 8;
    const int jj = j0 + c0;

    float cst[4] = {0.f, 0.f, 0.f, 0.f};
    unsigned gen = 0;

    for (int t = 0; t < TT; t++) {
        const __nv_bfloat16* ghi_in = g_ghi[t & 1];
        const __nv_bfloat16* glo_in = g_glo[t & 1];
        __nv_bfloat16* ghi_out = g_ghi[(t + 1) & 1];
        __nv_bfloat16* glo_out = g_glo[(t + 1) & 1];

        float2 xgv[2][4];
#pragma unroll
        for (int rp = 0; rp < 2; rp++) {
            size_t base = ((size_t)t * BB + (rp ? bB : bA)) * GG + jj;
#pragma unroll
            for (int g = 0; g < 4; g++)
                xgv[rp][g] = *(const float2*)&g_xg[base + (size_t)g * HH];
        }

        float acc[4][4];
#pragma unroll
        for (int nt = 0; nt < 4; nt++)
#pragma unroll
            for (int q = 0; q < 4; q++) acc[nt][q] = 0.f;

        rec_stage_w(wstg + 0 * RSTG_B, ghi_in, glo_in, wid, 0, lane);
        rec_stage_w(wstg + 1 * RSTG_B, ghi_in, glo_in, wid, 1, lane);
        rec_stage_w(wstg + 2 * RSTG_B, ghi_in, glo_in, wid, 2, lane);

        for (int c = 0; c < 16; c++) {
            if (c < 13) {
                rec_stage_w(wstg + ((c + 3) & 3) * RSTG_B, ghi_in, glo_in, wid, c + 3, lane);
                cp_wait<3>();
            } else if (c == 13) cp_wait<2>();
            else if (c == 14) cp_wait<1>();
            else cp_wait<0>();
            __syncwarp();

            const uint32_t abuf = wstg + (c & 3) * RSTG_B;
#pragma unroll
            for (int kl = 0; kl < 4; kl++) {
                const uint32_t Aad = abuf + a_off + kl * 32;
                const uint32_t kby = (uint32_t)(c * 64 + kl * 16) * 2;

                uint32_t ah[4], al[4], bh[4][2], bl[4][2];
                LDSM4(ah, Aad);
                LDSM4(al, Aad + RBUF_B);
                {
                    uint32_t t4[4];
                    LDSM4(t4, ws_hi + w_off + kby);
                    bh[0][0] = t4[0]; bh[0][1] = t4[1]; bh[1][0] = t4[2]; bh[1][1] = t4[3];
                    LDSM4(t4, ws_hi + 16 * WROW + w_off + kby);
                    bh[2][0] = t4[0]; bh[2][1] = t4[1]; bh[3][0] = t4[2]; bh[3][1] = t4[3];
                    LDSM4(t4, ws_lo + w_off + kby);
                    bl[0][0] = t4[0]; bl[0][1] = t4[1]; bl[1][0] = t4[2]; bl[1][1] = t4[3];
                    LDSM4(t4, ws_lo + 16 * WROW + w_off + kby);
                    bl[2][0] = t4[0]; bl[2][1] = t4[1]; bl[3][0] = t4[2]; bl[3][1] = t4[3];
                }
#pragma unroll
                for (int nt = 0; nt < 4; nt++) {
                    MMA16816(acc[nt], ah, bh[nt]);
                    MMA16816(acc[nt], al, bh[nt]);
                    MMA16816(acc[nt], ah, bl[nt]);
                }
            }
        }

#pragma unroll
        for (int rp = 0; rp < 2; rp++) {
            const int b = rp ? bB : bA;
            float hn[2];
#pragma unroll
            for (int cc = 0; cc < 2; cc++) {
                const int q = rp * 2 + cc;
                float pi = acc[0][q] + (cc ? xgv[rp][0].y : xgv[rp][0].x);
                float pf = acc[1][q] + (cc ? xgv[rp][1].y : xgv[rp][1].x);
                float pg = acc[2][q] + (cc ? xgv[rp][2].y : xgv[rp][2].x);
                float po = acc[3][q] + (cc ? xgv[rp][3].y : xgv[rp][3].x);
                float ig = 1.f / (1.f + expf(-pi));
                float fg = 1.f / (1.f + expf(-pf));
                float gc = tanhf(pg);
                float og = 1.f / (1.f + expf(-po));
                float cn = fg * cst[q] + ig * gc;
                cst[q] = cn;
                hn[cc] = og * tanhf(cn);
            }
            __nv_bfloat16 h0 = __float2bfloat16(hn[0]);
            __nv_bfloat16 h1 = __float2bfloat16(hn[1]);
            __nv_bfloat16 l0 = __float2bfloat16(hn[0] - __bfloat162float(h0));
            __nv_bfloat16 l1 = __float2bfloat16(hn[1] - __bfloat162float(h1));
            *(__nv_bfloat162*)&ghi_out[(size_t)b * HH + jj] = __nv_bfloat162(h0, h1);
            *(__nv_bfloat162*)&glo_out[(size_t)b * HH + jj] = __nv_bfloat162(l0, l1);
            if (LAYER == 0) {
                size_t arow = (((size_t)t * BB + b) << 10) + jj;
                *(__nv_bfloat162*)&g_Ahi[arow] = __nv_bfloat162(h0, h1);
                *(__nv_bfloat162*)&g_Alo[arow] = __nv_bfloat162(l0, l1);
            } else {
                *(float2*)&out_ext[((size_t)b * TT + t) * HH + jj] = make_float2(hn[0], hn[1]);
            }
        }

        // ---- grid barrier (atomic version, proven) ----
        __threadfence();
        __syncthreads();
        gen++;
        if (tid == 0) {
            if (atomicAdd(&g_cnt, 1u) == NCTA - 1) {
                g_cnt = 0u;
                __threadfence();
                *(volatile unsigned*)&g_gen = gen;
            } else {
                while (*(volatile unsigned*)&g_gen < gen) { }
                __threadfence();
            }
        }
        __syncthreads();
    }
}

// ---------------- launch ----------------
extern "C" void kernel_launch(void* const* d_in, const int* in_sizes, int n_in,
                              void* d_out, int out_size)
{
    (void)in_sizes; (void)n_in; (void)out_size;
    const float* x     = (const float*)d_in[0];
    const float* W_ih0 = (const float*)d_in[1];
    const float* W_hh0 = (const float*)d_in[2];
    const float* b_ih0 = (const float*)d_in[3];
    const float* b_hh0 = (const float*)d_in[4];
    const float* W_ih1 = (const float*)d_in[5];
    const float* W_hh1 = (const float*)d_in[6];
    const float* b_ih1 = (const float*)d_in[7];
    const float* b_hh1 = (const float*)d_in[8];
    float* out = (float*)d_out;

    cudaFuncSetAttribute(gemm_bf16_split, cudaFuncAttributeMaxDynamicSharedMemorySize, GEMM_SMEM);
    cudaFuncSetAttribute(lstm_rec_tc<0>, cudaFuncAttributeMaxDynamicSharedMemorySize, REC_SMEM);
    cudaFuncSetAttribute(lstm_rec_tc<1>, cudaFuncAttributeMaxDynamicSharedMemorySize, REC_SMEM);

    dim3 gemm_grid(GG / 128, (TT * BB) / 128);
    const int nch0 = (DIN + 63) / 64;   // 14 chunks cover k<896; rest is zero padding
    const int nch1 = 16;
    const size_t nW = (size_t)GG << 10;
    const int gridW = (int)((nW + 255) / 256);
    const int gridAll0 = (int)((NWELEM + NZ + NAELEM + 255) / 256);
    const int gridAll1 = (int)((NWELEM + NZ + 255) / 256);

    // ---- Layer 0 ----  (our launch index 3 = lstm_rec_tc<0> -> ncu capture target)
    convW<<<gridW, 256>>>(W_ih0, DIN);                                   // 0
    conv_all<<<gridAll0, 256>>>(x, W_hh0, 1);                            // 1: x->A, W_hh0->R, zero
    gemm_bf16_split<<<gemm_grid, 256, GEMM_SMEM>>>(b_ih0, b_hh0, nch0);  // 2
    lstm_rec_tc<0><<<NCTA, 128, REC_SMEM>>>(out);                        // 3 <- profiled
    // ---- Layer 1 ----
    convW<<<gridW, 256>>>(W_ih1, HH);                                    // 4
    conv_all<<<gridAll1, 256>>>(nullptr, W_hh1, 0);                      // 5: W_hh1->R, zero
    gemm_bf16_split<<<gemm_grid, 256, GEMM_SMEM>>>(b_ih1, b_hh1, nch1);  // 6
    lstm_rec_tc<1><<<NCTA, 128, REC_SMEM>>>(out);                        // 7
}

// round 12
// speedup vs baseline: 1.1528x; 1.0511x over previous
#include <cuda_runtime.h>
#include <cuda_bf16.h>
#include <math.h>
#include <stdint.h>

#define BB 64
#define TT 512
#define DIN 862
#define HH 1024
#define GG 4096

#define NCTA 128

// ---------------- scratch (allocation-free rule: __device__ globals) ----------------
static __device__ float g_xg[(size_t)TT * BB * GG];          // [T*B][G] gate preactivations
static __device__ unsigned g_gen;
static __device__ unsigned g_cnt;
static __device__ __nv_bfloat16 g_Ahi[(size_t)TT * BB * 1024];
static __device__ __nv_bfloat16 g_Alo[(size_t)TT * BB * 1024];
static __device__ __nv_bfloat16 g_Whi[(size_t)GG * 1024];    // input-GEMM weights
static __device__ __nv_bfloat16 g_Wlo[(size_t)GG * 1024];
static __device__ __nv_bfloat16 g_Rhi[(size_t)GG * 1024];    // recurrent weights
static __device__ __nv_bfloat16 g_Rlo[(size_t)GG * 1024];
static __device__ __nv_bfloat16 g_ghi[2][BB * HH];           // h state bf16 hi, ping-pong [b][k]
static __device__ __nv_bfloat16 g_glo[2][BB * HH];           // h state bf16 lo

// ---------------- PTX helpers ----------------
__device__ __forceinline__ uint32_t smem_u32(const void* p) {
    uint32_t a;
    asm("{ .reg .u64 t; cvta.to.shared.u64 t, %1; cvt.u32.u64 %0, t; }" : "=r"(a) : "l"(p));
    return a;
}
__device__ __forceinline__ void cp_async16(uint32_t dst, const void* src) {
    asm volatile("cp.async.cg.shared.global [%0], [%1], 16;" :: "r"(dst), "l"(src));
}
__device__ __forceinline__ void cp_commit() { asm volatile("cp.async.commit_group;" ::: "memory"); }
template<int N> __device__ __forceinline__ void cp_wait() { asm volatile("cp.async.wait_group %0;" :: "n"(N) : "memory"); }

#define LDSM4(r, addr) \
    asm volatile("ldmatrix.sync.aligned.m8n8.x4.shared.b16 {%0,%1,%2,%3}, [%4];" \
        : "=r"((r)[0]), "=r"((r)[1]), "=r"((r)[2]), "=r"((r)[3]) : "r"(addr))

#define MMA16816(c, a, b) \
    asm volatile("mma.sync.aligned.m16n8k16.row.col.f32.bf16.bf16.f32 " \
        "{%0,%1,%2,%3}, {%4,%5,%6,%7}, {%8,%9}, {%0,%1,%2,%3};" \
        : "+f"((c)[0]), "+f"((c)[1]), "+f"((c)[2]), "+f"((c)[3]) \
        : "r"((a)[0]), "r"((a)[1]), "r"((a)[2]), "r"((a)[3]), "r"((b)[0]), "r"((b)[1]))

// ---------------- fp32 -> split bf16 conversions ----------------
__global__ void convW(const float* __restrict__ src, int K) {
    size_t i = (size_t)blockIdx.x * blockDim.x + threadIdx.x;
    if (i >= ((size_t)GG << 10)) return;
    int k = (int)(i & 1023);
    size_t row = i >> 10;
    float v = (k < K) ? src[row * K + k] : 0.f;
    __nv_bfloat16 h = __float2bfloat16(v);
    g_Whi[i] = h;
    g_Wlo[i] = __float2bfloat16(v - __bfloat162float(h));
}

#define NWELEM ((size_t)GG << 10)
#define NZ 131072
#define NAELEM ((size_t)TT * BB << 10)
__global__ void conv_all(const float* __restrict__ x, const float* __restrict__ Whh, int has_x) {
    size_t i = (size_t)blockIdx.x * blockDim.x + threadIdx.x;
    if (i < NWELEM) {
        int k = (int)(i & 1023);
        size_t row = i >> 10;
        float v = Whh[(row << 10) + k];
        __nv_bfloat16 h = __float2bfloat16(v);
        g_Rhi[i] = h;
        g_Rlo[i] = __float2bfloat16(v - __bfloat162float(h));
    } else if (i < NWELEM + NZ) {
        size_t z = i - NWELEM;
        if (z == 0) { g_gen = 0u; g_cnt = 0u; }
        if (z < 65536) ((uint32_t*)g_ghi)[z] = 0u;
        else           ((uint32_t*)g_glo)[z - 65536] = 0u;
    } else if (has_x) {
        size_t j = i - NWELEM - NZ;
        if (j < NAELEM) {
            int k = (int)(j & 1023);
            size_t row = j >> 10;
            int t = (int)(row >> 6), b = (int)(row & 63);
            float v = (k < DIN) ? x[((size_t)b * TT + t) * DIN + k] : 0.f;
            __nv_bfloat16 h = __float2bfloat16(v);
            g_Ahi[j] = h;
            g_Alo[j] = __float2bfloat16(v - __bfloat162float(h));
        }
    }
}

// ---------------- mma.sync bf16 split GEMM (round-9, passing) ----------------
#define TROW 144
#define TILE_B (128 * TROW)
#define STAGE_B (4 * TILE_B)
#define GEMM_SMEM (2 * STAGE_B + 512)

__device__ __forceinline__ void gemm_issue_loads(uint32_t sbase, int c, int m0, int n0, int tid) {
    const __nv_bfloat16* ptrs[4] = { g_Ahi, g_Alo, g_Whi, g_Wlo };
#pragma unroll
    for (int q = 0; q < 4; q++) {
        const __nv_bfloat16* p = ptrs[q];
        int rowbase = (q < 2) ? m0 : n0;
        uint32_t tb = sbase + q * TILE_B;
#pragma unroll
        for (int i = 0; i < 4; i++) {
            int idx = tid + i * 256;
            int r = idx >> 3, s = idx & 7;
            cp_async16(tb + r * TROW + s * 16,
                       p + (((size_t)(rowbase + r)) << 10) + (c << 6) + (s << 3));
        }
    }
}

__global__ void __launch_bounds__(256, 1)
gemm_bf16_split(const float* __restrict__ b1, const float* __restrict__ b2, int nch)
{
    extern __shared__ char smraw[];
    uint32_t sbase = smem_u32(smraw);
    float* sbias = (float*)(smraw + 2 * STAGE_B);

    const int tid = threadIdx.x;
    const int lane = tid & 31, wid = tid >> 5;
    const int n0 = blockIdx.x * 128;
    const int m0 = blockIdx.y * 128;
    const int wm = (wid >> 2) * 64;
    const int wn = (wid & 3) * 32;

    if (tid < 128) sbias[tid] = b1[n0 + tid] + b2[n0 + tid];

    float acc[4][4][4];
#pragma unroll
    for (int i = 0; i < 4; i++)
#pragma unroll
        for (int j = 0; j < 4; j++)
#pragma unroll
            for (int q = 0; q < 4; q++) acc[i][j][q] = 0.f;

    gemm_issue_loads(sbase, 0, m0, n0, tid);
    cp_commit();

    const uint32_t a_row = wm + (lane & 15);
    const uint32_t a_coh = (lane >> 4) << 4;
    const uint32_t b_rlo = (lane >> 4) * 8 + (lane & 7);
    const uint32_t b_coh = ((lane >> 3) & 1) << 4;

    for (int c = 0; c < nch; c++) {
        if (c < nch - 1) {
            gemm_issue_loads(sbase + ((c + 1) & 1) * STAGE_B, c + 1, m0, n0, tid);
            cp_commit();
            cp_wait<1>();
        } else {
            cp_wait<0>();
        }
        __syncthreads();

        const uint32_t buf = sbase + (c & 1) * STAGE_B;
        const uint32_t Ahi_b = buf;
        const uint32_t Alo_b = buf + TILE_B;
        const uint32_t Whi_b = buf + 2 * TILE_B;
        const uint32_t Wlo_b = buf + 3 * TILE_B;

#pragma unroll
        for (int ks = 0; ks < 4; ks++) {
            const uint32_t kso = ks * 32;
            uint32_t ah[4][4], bh[4][2];
#pragma unroll
            for (int mt = 0; mt < 4; mt++)
                LDSM4(ah[mt], Ahi_b + (a_row + mt * 16) * TROW + kso + a_coh);
#pragma unroll
            for (int g = 0; g < 2; g++) {
                uint32_t t4[4];
                LDSM4(t4, Whi_b + (wn + g * 16 + b_rlo) * TROW + kso + b_coh);
                bh[g * 2][0] = t4[0]; bh[g * 2][1] = t4[1];
                bh[g * 2 + 1][0] = t4[2]; bh[g * 2 + 1][1] = t4[3];
            }
#pragma unroll
            for (int mt = 0; mt < 4; mt++)
#pragma unroll
                for (int nt = 0; nt < 4; nt++)
                    MMA16816(acc[mt][nt], ah[mt], bh[nt]);

            uint32_t bl[4][2];
#pragma unroll
            for (int g = 0; g < 2; g++) {
                uint32_t t4[4];
                LDSM4(t4, Wlo_b + (wn + g * 16 + b_rlo) * TROW + kso + b_coh);
                bl[g * 2][0] = t4[0]; bl[g * 2][1] = t4[1];
                bl[g * 2 + 1][0] = t4[2]; bl[g * 2 + 1][1] = t4[3];
            }
#pragma unroll
            for (int mt = 0; mt < 4; mt++)
#pragma unroll
                for (int nt = 0; nt < 4; nt++)
                    MMA16816(acc[mt][nt], ah[mt], bl[nt]);

            uint32_t al[4][4];
#pragma unroll
            for (int mt = 0; mt < 4; mt++)
                LDSM4(al[mt], Alo_b + (a_row + mt * 16) * TROW + kso + a_coh);
#pragma unroll
            for (int mt = 0; mt < 4; mt++)
#pragma unroll
                for (int nt = 0; nt < 4; nt++)
                    MMA16816(acc[mt][nt], al[mt], bh[nt]);
        }
        __syncthreads();
    }

    const int r_lo = lane >> 2;
    const int cpos = (lane & 3) * 2;
#pragma unroll
    for (int mt = 0; mt < 4; mt++) {
        int row0 = m0 + wm + mt * 16 + r_lo;
#pragma unroll
        for (int nt = 0; nt < 4; nt++) {
            int cl = wn + nt * 8 + cpos;
            float bx = sbias[cl], by = sbias[cl + 1];
            float2 v0 = make_float2(acc[mt][nt][0] + bx, acc[mt][nt][1] + by);
            float2 v1 = make_float2(acc[mt][nt][2] + bx, acc[mt][nt][3] + by);
            *(float2*)&g_xg[(size_t)row0 * GG + n0 + cl] = v0;
            *(float2*)&g_xg[(size_t)(row0 + 8) * GG + n0 + cl] = v1;
        }
    }
}

// ---------------- persistent recurrence: 8 warps, k-split pairs ----------------
// 128 CTAs x 256 threads. Warp wb in {0..3} + partner wb+4 share batch rows
// [wb*16, wb*16+16): wb sums k in [0,512), wb+4 sums k in [512,1024).
// Partials combined via smem; warps 0-3 run the pointwise update.
#define WROW 2064
#define WS_B (32 * WROW)                // 66048 per array
#define RROW 144
#define RBUF_B (16 * RROW)              // 2304
#define RSTG_B (2 * RBUF_B)             // 4608 (hi + lo)
#define NBUF 2
#define WARP_STG (NBUF * RSTG_B)        // 9216
#define CMB_OFF (2 * WS_B + 8 * WARP_STG)   // 205824
#define CMB_B (4 * 32 * 16 * 4)             // 8192
#define REC_SMEM (CMB_OFF + CMB_B)          // 214016

__device__ __forceinline__ void rec_stage_w(uint32_t dst, const __nv_bfloat16* ghi,
                                            const __nv_bfloat16* glo,
                                            int wb, int wk, int c, int lane) {
#pragma unroll
    for (int i = 0; i < 4; i++) {
        int idx = lane + i * 32;
        int r = idx >> 3, s = idx & 7;
        uint32_t d = dst + r * RROW + s * 16;
        size_t so = (size_t)(wb * 16 + r) * 1024 + wk * 512 + c * 64 + s * 8;
        cp_async16(d, ghi + so);
        cp_async16(d + RBUF_B, glo + so);
    }
    cp_commit();
}

template<int LAYER>
__global__ void __launch_bounds__(256, 1)
lstm_rec_tc(float* __restrict__ out_ext)
{
    extern __shared__ char smraw[];
    const uint32_t sb = smem_u32(smraw);
    const uint32_t ws_hi = sb;
    const uint32_t ws_lo = sb + WS_B;
    float* cmb = (float*)(smraw + CMB_OFF);

    const int tid = threadIdx.x;
    const int lane = tid & 31, wid = tid >> 5;
    const int wb = wid & 3;          // batch group
    const int wk = wid >> 2;         // k half
    const int j0 = blockIdx.x * 8;
    const uint32_t wstg = sb + 2 * WS_B + wid * WARP_STG;

    // Load W tiles: threads 0-127 fill ws_hi, threads 128-255 fill ws_lo
    {
        const int tt = tid & 127;
        const __nv_bfloat16* src = (tid < 128) ? g_Rhi : g_Rlo;
        const uint32_t dstb = (tid < 128) ? ws_hi : ws_lo;
#pragma unroll 4
        for (int n = 0; n < 32; n++) {
            int grow = ((n >> 3) << 10) + j0 + (n & 7);
            cp_async16(dstb + n * WROW + tt * 16, src + ((size_t)grow << 10) + tt * 8);
        }
    }
    cp_commit(); cp_wait<0>();
    __syncthreads();

    const uint32_t a_off = (lane & 15) * RROW + ((lane >> 4) << 4);
    const uint32_t w_off = ((lane >> 4) * 8 + (lane & 7)) * WROW + (((lane >> 3) & 1) << 4);

    // cell mapping (warps 0-3 only): acc[nt][0]=(r0,c0) [1]=(r0,c1) [2]=(r0+8,c0) [3]=(r0+8,c1)
    const int r0 = lane >> 2;
    const int c0 = (lane & 3) * 2;
    const int bA = wb * 16 + r0;
    const int bB = bA + 8;
    const int jj = j0 + c0;

    float cst[4] = {0.f, 0.f, 0.f, 0.f};
    unsigned gen = 0;

    for (int t = 0; t < TT; t++) {
        const __nv_bfloat16* ghi_in = g_ghi[t & 1];
        const __nv_bfloat16* glo_in = g_glo[t & 1];
        __nv_bfloat16* ghi_out = g_ghi[(t + 1) & 1];
        __nv_bfloat16* glo_out = g_glo[(t + 1) & 1];

        float2 xgv[2][4];
        if (wk == 0) {
#pragma unroll
            for (int rp = 0; rp < 2; rp++) {
                size_t base = ((size_t)t * BB + (rp ? bB : bA)) * GG + jj;
#pragma unroll
                for (int g = 0; g < 4; g++)
                    xgv[rp][g] = *(const float2*)&g_xg[base + (size_t)g * HH];
            }
        }

        float acc[4][4];
#pragma unroll
        for (int nt = 0; nt < 4; nt++)
#pragma unroll
            for (int q = 0; q < 4; q++) acc[nt][q] = 0.f;

        rec_stage_w(wstg, ghi_in, glo_in, wb, wk, 0, lane);

        for (int c = 0; c < 8; c++) {
            if (c < 7) {
                rec_stage_w(wstg + ((c + 1) & 1) * RSTG_B, ghi_in, glo_in, wb, wk, c + 1, lane);
                cp_wait<1>();
            } else {
                cp_wait<0>();
            }
            __syncwarp();

            const uint32_t abuf = wstg + (c & 1) * RSTG_B;
#pragma unroll
            for (int kl = 0; kl < 4; kl++) {
                const uint32_t Aad = abuf + a_off + kl * 32;
                const uint32_t kby = (uint32_t)(wk * 512 + c * 64 + kl * 16) * 2;

                uint32_t ah[4], al[4], bh[4][2], bl[4][2];
                LDSM4(ah, Aad);
                LDSM4(al, Aad + RBUF_B);
                {
                    uint32_t t4[4];
                    LDSM4(t4, ws_hi + w_off + kby);
                    bh[0][0] = t4[0]; bh[0][1] = t4[1]; bh[1][0] = t4[2]; bh[1][1] = t4[3];
                    LDSM4(t4, ws_hi + 16 * WROW + w_off + kby);
                    bh[2][0] = t4[0]; bh[2][1] = t4[1]; bh[3][0] = t4[2]; bh[3][1] = t4[3];
                    LDSM4(t4, ws_lo + w_off + kby);
                    bl[0][0] = t4[0]; bl[0][1] = t4[1]; bl[1][0] = t4[2]; bl[1][1] = t4[3];
                    LDSM4(t4, ws_lo + 16 * WROW + w_off + kby);
                    bl[2][0] = t4[0]; bl[2][1] = t4[1]; bl[3][0] = t4[2]; bl[3][1] = t4[3];
                }
#pragma unroll
                for (int nt = 0; nt < 4; nt++) {
                    MMA16816(acc[nt], ah, bh[nt]);
                    MMA16816(acc[nt], al, bh[nt]);
                    MMA16816(acc[nt], ah, bl[nt]);
                }
            }
        }

        // combine k-halves: warps 4-7 publish partials, warps 0-3 add
        if (wk == 1) {
            float* p = cmb + (wb * 32 + lane) * 16;
#pragma unroll
            for (int nt = 0; nt < 4; nt++)
                *(float4*)(p + nt * 4) = make_float4(acc[nt][0], acc[nt][1], acc[nt][2], acc[nt][3]);
        }
        __syncthreads();

        if (wk == 0) {
            float* p = cmb + (wb * 32 + lane) * 16;
#pragma unroll
            for (int nt = 0; nt < 4; nt++) {
                float4 v = *(float4*)(p + nt * 4);
                acc[nt][0] += v.x; acc[nt][1] += v.y; acc[nt][2] += v.z; acc[nt][3] += v.w;
            }

#pragma unroll
            for (int rp = 0; rp < 2; rp++) {
                const int b = rp ? bB : bA;
                float hn[2];
#pragma unroll
                for (int cc = 0; cc < 2; cc++) {
                    const int q = rp * 2 + cc;
                    float pi = acc[0][q] + (cc ? xgv[rp][0].y : xgv[rp][0].x);
                    float pf = acc[1][q] + (cc ? xgv[rp][1].y : xgv[rp][1].x);
                    float pg = acc[2][q] + (cc ? xgv[rp][2].y : xgv[rp][2].x);
                    float po = acc[3][q] + (cc ? xgv[rp][3].y : xgv[rp][3].x);
                    float ig = 1.f / (1.f + expf(-pi));
                    float fg = 1.f / (1.f + expf(-pf));
                    float gc = tanhf(pg);
                    float og = 1.f / (1.f + expf(-po));
                    float cn = fg * cst[q] + ig * gc;
                    cst[q] = cn;
                    hn[cc] = og * tanhf(cn);
                }
                __nv_bfloat16 h0 = __float2bfloat16(hn[0]);
                __nv_bfloat16 h1 = __float2bfloat16(hn[1]);
                __nv_bfloat16 l0 = __float2bfloat16(hn[0] - __bfloat162float(h0));
                __nv_bfloat16 l1 = __float2bfloat16(hn[1] - __bfloat162float(h1));
                *(__nv_bfloat162*)&ghi_out[(size_t)b * HH + jj] = __nv_bfloat162(h0, h1);
                *(__nv_bfloat162*)&glo_out[(size_t)b * HH + jj] = __nv_bfloat162(l0, l1);
                if (LAYER == 0) {
                    size_t arow = (((size_t)t * BB + b) << 10) + jj;
                    *(__nv_bfloat162*)&g_Ahi[arow] = __nv_bfloat162(h0, h1);
                    *(__nv_bfloat162*)&g_Alo[arow] = __nv_bfloat162(l0, l1);
                } else {
                    *(float2*)&out_ext[((size_t)b * TT + t) * HH + jj] = make_float2(hn[0], hn[1]);
                }
            }
        }

        // ---- grid barrier (atomic version, proven) ----
        __threadfence();
        __syncthreads();
        gen++;
        if (tid == 0) {
            if (atomicAdd(&g_cnt, 1u) == NCTA - 1) {
                g_cnt = 0u;
                __threadfence();
                *(volatile unsigned*)&g_gen = gen;
            } else {
                while (*(volatile unsigned*)&g_gen < gen) { }
                __threadfence();
            }
        }
        __syncthreads();
    }
}

// ---------------- launch ----------------
extern "C" void kernel_launch(void* const* d_in, const int* in_sizes, int n_in,
                              void* d_out, int out_size)
{
    (void)in_sizes; (void)n_in; (void)out_size;
    const float* x     = (const float*)d_in[0];
    const float* W_ih0 = (const float*)d_in[1];
    const float* W_hh0 = (const float*)d_in[2];
    const float* b_ih0 = (const float*)d_in[3];
    const float* b_hh0 = (const float*)d_in[4];
    const float* W_ih1 = (const float*)d_in[5];
    const float* W_hh1 = (const float*)d_in[6];
    const float* b_ih1 = (const float*)d_in[7];
    const float* b_hh1 = (const float*)d_in[8];
    float* out = (float*)d_out;

    cudaFuncSetAttribute(gemm_bf16_split, cudaFuncAttributeMaxDynamicSharedMemorySize, GEMM_SMEM);
    cudaFuncSetAttribute(lstm_rec_tc<0>, cudaFuncAttributeMaxDynamicSharedMemorySize, REC_SMEM);
    cudaFuncSetAttribute(lstm_rec_tc<1>, cudaFuncAttributeMaxDynamicSharedMemorySize, REC_SMEM);

    dim3 gemm_grid(GG / 128, (TT * BB) / 128);
    const int nch0 = (DIN + 63) / 64;
    const int nch1 = 16;
    const size_t nW = (size_t)GG << 10;
    const int gridW = (int)((nW + 255) / 256);
    const int gridAll0 = (int)((NWELEM + NZ + NAELEM + 255) / 256);
    const int gridAll1 = (int)((NWELEM + NZ + 255) / 256);

    // ---- Layer 0 ----  (our launch index 3 = lstm_rec_tc<0> -> ncu capture target)
    convW<<<gridW, 256>>>(W_ih0, DIN);                                   // 0
    conv_all<<<gridAll0, 256>>>(x, W_hh0, 1);                            // 1
    gemm_bf16_split<<<gemm_grid, 256, GEMM_SMEM>>>(b_ih0, b_hh0, nch0);  // 2
    lstm_rec_tc<0><<<NCTA, 256, REC_SMEM>>>(out);                        // 3 <- profiled
    // ---- Layer 1 ----
    convW<<<gridW, 256>>>(W_ih1, HH);                                    // 4
    conv_all<<<gridAll1, 256>>>(nullptr, W_hh1, 0);                      // 5
    gemm_bf16_split<<<gemm_grid, 256, GEMM_SMEM>>>(b_ih1, b_hh1, nch1);  // 6
    lstm_rec_tc<1><<<NCTA, 256, REC_SMEM>>>(out);                        // 7
}